// round 14
// baseline (speedup 1.0000x reference)
#include <cuda_runtime.h>
#include <cuda_bf16.h>

#define NB 64
#define IN_DIM 1024
#define OUT_DIM 1024
#define STEPS 100
#define TSTEPS 99              // S-1 projection steps
#define M_ROWS (TSTEPS * NB)   // 6336 = 198 * 32 exactly
#define K_DIM 1024
#define N_DIM 1024
#define NCHUNK (K_DIM / 16)    // 64 chunks of 16

__device__ float g_xs[(size_t)M_ROWS * K_DIM];    // xs[(t*64+b)][i]
__device__ float g_proj[(size_t)M_ROWS * N_DIM];  // proj[(t*64+b)][o]

// ---------------------------------------------------------------------------
// Kernel 1: transpose x [B][IN][S] (t fastest) -> g_xs[(t*NB+b)][i]
// ---------------------------------------------------------------------------
__global__ void xpose_kernel(const float* __restrict__ x) {
    __shared__ float tile[32][33];
    int b  = blockIdx.z;
    int i0 = blockIdx.y * 32;
    int t0 = blockIdx.x * 32;
    int tx = threadIdx.x, ty = threadIdx.y;

    int t = t0 + tx;
    int i = i0 + ty;
    float v = 0.0f;
    if (t < STEPS)
        v = x[((size_t)b * IN_DIM + i) * STEPS + t];
    tile[ty][tx] = v;
    __syncthreads();

    int tt = t0 + ty;
    int ii = i0 + tx;
    if (tt < TSTEPS)
        g_xs[((size_t)tt * NB + b) * K_DIM + ii] = tile[tx][ty];
}

// ---------------------------------------------------------------------------
// Kernel 2: EXPERIMENT R14 — bitwise model of cuBLAS FP32-emulation (bf16x9)
// on tensor cores, software-emulated:
//   w = w0 + w1 + w2 (bf16 RN splits, exact for f32 inputs)
//   x in {0,1} -> x splits are trivial, all products EXACT
//   per output: acc = 0;
//     for chunk c = 0..63 (k = 16c..16c+15, ascending):
//       for split j = 0,1,2:
//         acc = rn_f32( acc + S_exact(chunk, j) )   // one rounding per MMA
// S_exact computed as f32 double-float (TwoSum running sum), folded into acc
// with a single effective rounding (Dekker add).
// Block 32m x 32n, 256 thr: warp w -> rows 4w..4w+3 (a warp-uniform), lane=n.
// ---------------------------------------------------------------------------
#define TWOSUM(s, e, p) do {                                   \
    float _t = __fadd_rn((s), (p));                            \
    float _z = __fadd_rn(_t, -(s));                            \
    float _e1 = __fadd_rn((s), -__fadd_rn(_t, -_z));           \
    float _e2 = __fadd_rn((p), -_z);                           \
    (e) = __fadd_rn((e), __fadd_rn(_e1, _e2));                 \
    (s) = _t;                                                  \
} while (0)

// acc <- rn(acc + (s + e)) up to double-rounding corner cases
#define FOLD(acc, s, e) do {                                   \
    float _t = __fadd_rn((acc), (s));                          \
    float _b = __fadd_rn(_t, -(acc));                          \
    float _err = __fadd_rn(__fadd_rn((acc), -__fadd_rn(_t, -_b)), \
                           __fadd_rn((s), -_b));               \
    (acc) = __fadd_rn(_t, __fadd_rn(_err, (e)));               \
} while (0)

__global__ __launch_bounds__(256, 2) void gemm_kernel(const float* __restrict__ W) {
    __shared__ float As[16][33];
    __shared__ float B0[16][33];
    __shared__ float B1[16][33];
    __shared__ float B2[16][33];

    int m0 = blockIdx.y * 32;
    int n0 = blockIdx.x * 32;
    int tid  = threadIdx.x;
    int lane = tid & 31;          // n col
    int warp = tid >> 5;          // 0..7 -> m rows [4w, 4w+4)

    int l_row = tid & 31;
    int l_k2  = (tid >> 5) * 2;   // 0,2,...,14

    const float* Aptr = g_xs + (size_t)(m0 + l_row) * K_DIM + l_k2;
    const float* Wptr = W    + (size_t)(n0 + l_row) * K_DIM + l_k2;

    float acc[4] = {0.f, 0.f, 0.f, 0.f};

    for (int c = 0; c < NCHUNK; c++) {
        // load A chunk (2 floats/thread)
        float2 av = *(const float2*)(Aptr + c * 16);
        As[l_k2 + 0][l_row] = av.x;
        As[l_k2 + 1][l_row] = av.y;
        // load W chunk, split into bf16 triple (exact): w = w0 + w1 + w2
        float2 wv = *(const float2*)(Wptr + c * 16);
#pragma unroll
        for (int u = 0; u < 2; u++) {
            float w  = (u == 0) ? wv.x : wv.y;
            float w0 = __bfloat162float(__float2bfloat16(w));
            float r1 = __fadd_rn(w, -w0);                      // exact
            float w1 = __bfloat162float(__float2bfloat16(r1));
            float r2 = __fadd_rn(r1, -w1);                     // exact
            float w2 = __bfloat162float(__float2bfloat16(r2));
            B0[l_k2 + u][l_row] = w0;
            B1[l_k2 + u][l_row] = w1;
            B2[l_k2 + u][l_row] = w2;
        }
        __syncthreads();

        // exact chunk sums per (row, split) as double-float (s,e)
        float s[4][3], e[4][3];
#pragma unroll
        for (int r = 0; r < 4; r++)
#pragma unroll
            for (int j = 0; j < 3; j++) { s[r][j] = 0.f; e[r][j] = 0.f; }

#pragma unroll 4
        for (int kk = 0; kk < 16; kk++) {
            float b0 = B0[kk][lane];
            float b1 = B1[kk][lane];
            float b2 = B2[kk][lane];
#pragma unroll
            for (int r = 0; r < 4; r++) {
                float a = As[kk][warp * 4 + r];   // warp-uniform broadcast
                if (a != 0.0f) {                  // non-divergent branch
                    TWOSUM(s[r][0], e[r][0], b0);
                    TWOSUM(s[r][1], e[r][1], b1);
                    TWOSUM(s[r][2], e[r][2], b2);
                }
            }
        }

        // fold: one f32 rounding per (chunk, split), splits hi -> lo
#pragma unroll
        for (int r = 0; r < 4; r++) {
            FOLD(acc[r], s[r][0], e[r][0]);
            FOLD(acc[r], s[r][1], e[r][1]);
            FOLD(acc[r], s[r][2], e[r][2]);
        }
        __syncthreads();
    }

#pragma unroll
    for (int r = 0; r < 4; r++)
        g_proj[(size_t)(m0 + warp * 4 + r) * N_DIM + n0 + lane] = acc[r];
}

// ---------------------------------------------------------------------------
// Kernel 3: LIF scan, pinned (fully unfused):
//   Vn = rn(rn(a_m*V) + rn(b_m*I));  In = rn(rn(a_s*I) + p)
// ---------------------------------------------------------------------------
__global__ void scan_kernel(float* __restrict__ out) {
    int gid = blockIdx.x * blockDim.x + threadIdx.x;
    int b = gid >> 10;
    int o = gid & 1023;

    const float a_m = 0.95f, b_m = 0.05f, a_s = 0.8f;

    float* op = out + ((size_t)b * OUT_DIM + o) * STEPS;
    const float* pp = g_proj + (size_t)b * N_DIM + o;

    float V = 0.0f, I = 0.0f;
    op[0] = 0.0f;
    for (int t = 0; t < TSTEPS; t++) {
        float p  = pp[(size_t)t * NB * N_DIM];
        float Vn = __fadd_rn(__fmul_rn(a_m, V), __fmul_rn(b_m, I));
        float In = __fadd_rn(__fmul_rn(a_s, I), p);
        bool  ss = (Vn > 1.0f);
        op[t + 1] = ss ? 1.0f : 0.0f;
        V = ss ? 0.0f : Vn;
        I = In;
    }
}

// ---------------------------------------------------------------------------
extern "C" void kernel_launch(void* const* d_in, const int* in_sizes, int n_in,
                              void* d_out, int out_size) {
    const float* x = (const float*)d_in[0];   // [64][1024][100]
    const float* W = (const float*)d_in[1];   // [1024][1024]
    float* out = (float*)d_out;               // [64][1024][100]

    (void)in_sizes; (void)n_in; (void)out_size;

    dim3 tb(32, 32);
    dim3 tg(4, IN_DIM / 32, NB);
    xpose_kernel<<<tg, tb>>>(x);

    dim3 gg(N_DIM / 32, M_ROWS / 32);          // (32, 198)
    gemm_kernel<<<gg, 256>>>(W);

    scan_kernel<<<(NB * OUT_DIM) / 256, 256>>>(out);
}

// round 16
// speedup vs baseline: 2.0994x; 2.0994x over previous
#include <cuda_runtime.h>
#include <cuda_bf16.h>
#include <cstdint>

#define NB 64
#define IN_DIM 1024
#define OUT_DIM 1024
#define STEPS 100
#define TSTEPS 99
#define M_ROWS (TSTEPS * NB)    // 6336 = 198 * 32
#define K_DIM 1024
#define N_DIM 1024

__device__ uint32_t g_xm[(size_t)M_ROWS * 32];      // [m][j] bits i=32j..32j+31
__device__ float4   g_wp[(size_t)N_DIM * K_DIM];    // (w0,w1,w2,0) packed
__device__ float    g_proj[(size_t)M_ROWS * N_DIM];
__device__ float    g_spk[(size_t)TSTEPS * NB * OUT_DIM];

// Ladder constants per split (|partial| bounds: 1.3, 2^-8.6, 2^-17.6)
#define C0 4.0f
#define C1 0.015625f       // 2^-6
#define C2 6.103515625e-5f // 2^-14

// Exact Fast2Sum into (s,e), valid since exp(s)>=exp(b) by ladder seeding.
// All adds as FFMA-imm (rt=1) — bitwise rn(a+b).
#define LADD(s, e, b) do {                          \
    float _t  = __fmaf_rn((b),  1.0f, (s));         \
    float _z  = __fmaf_rn((s), -1.0f, _t);          \
    float _er = __fmaf_rn(_z,  -1.0f, (b));         \
    (e) = __fmaf_rn(_er, 1.0f, (e));                \
    (s) = _t;                                       \
} while (0)

// Identical arithmetic to the R14 (bitwise-passing) FOLD, in FFMA-imm form:
// t=acc+s; b=t-acc; err=(acc-(t-b))+(s-b); acc=t+(err+e)
#define FOLD(acc, s, e) do {                        \
    float _t  = __fmaf_rn((s),  1.0f, (acc));       \
    float _b  = __fmaf_rn((acc), -1.0f, _t);        \
    float _x  = __fmaf_rn(_b,  -1.0f, _t);          \
    float _e1 = __fmaf_rn(_x,  -1.0f, (acc));       \
    float _e2 = __fmaf_rn(_b,  -1.0f, (s));         \
    float _er = __fmaf_rn(_e1,  1.0f, _e2);         \
    (acc) = __fmaf_rn(__fmaf_rn((e), 1.0f, _er), 1.0f, _t); \
} while (0)

// ---------------------------------------------------------------------------
// Kernel 1: build activation bitmasks. One warp per m=(t*64+b).
// bit l of word j = (x[b][32j+l][t] != 0)
// ---------------------------------------------------------------------------
__global__ void mask_kernel(const float* __restrict__ x) {
    int m = blockIdx.x * 8 + (threadIdx.x >> 5);
    if (m >= M_ROWS) return;
    int lane = threadIdx.x & 31;
    int t = m >> 6, b = m & 63;
    const float* xb = x + (size_t)b * IN_DIM * STEPS + t;
    uint32_t* dst = g_xm + (size_t)m * 32;
#pragma unroll 4
    for (int j = 0; j < 32; j++) {
        float v = xb[(size_t)(j * 32 + lane) * STEPS];
        uint32_t msk = __ballot_sync(0xffffffffu, v != 0.0f);
        if (lane == 0) dst[j] = msk;
    }
}

// ---------------------------------------------------------------------------
// Kernel 2: split W into exact bf16 triple, packed as float4 (w0,w1,w2,0)
// ---------------------------------------------------------------------------
__global__ void wsplit_kernel(const float* __restrict__ W) {
    int i = blockIdx.x * 256 + threadIdx.x;
    float w  = W[i];
    float w0 = __bfloat162float(__float2bfloat16(w));
    float r1 = __fadd_rn(w, -w0);                    // exact
    float w1 = __bfloat162float(__float2bfloat16(r1));
    float r2 = __fadd_rn(r1, -w1);                   // exact
    float w2 = __bfloat162float(__float2bfloat16(r2)); // exact (f32 = 3x8 bits)
    g_wp[i] = make_float4(w0, w1, w2, 0.0f);
}

// ---------------------------------------------------------------------------
// Kernel 3: bitwise bf16x9-emulation GEMM, mask-sparse, ladder-compensated.
// Block: 32m x 32n, 128 threads = 4 warps; warp w -> rows 8w..8w+7, lane = n.
// Per chunk (16 k, ascending) per row: exact sums S0,S1,S2, folded hi->lo
// with one RN each — identical fold semantics to the R14 bitwise pass.
// ---------------------------------------------------------------------------
__global__ __launch_bounds__(128) void gemm_kernel() {
    __shared__ uint32_t Ms[32][32];        // masks: [row][j]
    __shared__ float4   Bsf[16][33];       // chunk W triple: [k][n], padded

    int m0 = blockIdx.y * 32;
    int n0 = blockIdx.x * 32;
    int tid  = threadIdx.x;
    int lane = tid & 31;
    int wid  = tid >> 5;                   // 0..3

    // stage masks once
#pragma unroll
    for (int i = tid; i < 32 * 32; i += 128)
        Ms[i >> 5][i & 31] = g_xm[(size_t)(m0 + (i >> 5)) * 32 + (i & 31)];

    float acc[8];
#pragma unroll
    for (int r = 0; r < 8; r++) acc[r] = 0.0f;

    for (int c = 0; c < 64; c++) {
        __syncthreads();
        // stage W chunk: 512 float4, 4 per thread, k-fastest (coalesced)
#pragma unroll
        for (int i = 0; i < 4; i++) {
            int idx = tid + i * 128;
            int n = idx >> 4, k = idx & 15;
            Bsf[k][n] = g_wp[(size_t)(n0 + n) * K_DIM + c * 16 + k];
        }
        __syncthreads();

        int jj = c >> 1, sh = (c & 1) << 4;
#pragma unroll
        for (int r = 0; r < 8; r++) {
            uint32_t mr = (Ms[wid * 8 + r][jj] >> sh) & 0xFFFFu;
            float s0 = C0, s1 = C1, s2 = C2;
            float e0 = 0.f, e1 = 0.f, e2 = 0.f;
            while (mr) {                      // warp-uniform loop
                int k = __ffs(mr) - 1;
                mr &= mr - 1;
                float4 wv = Bsf[k][lane];
                LADD(s0, e0, wv.x);
                LADD(s1, e1, wv.y);
                LADD(s2, e2, wv.z);
            }
            float S0 = __fmaf_rn(s0, 1.0f, -C0);   // exact (Sterbenz)
            float S1 = __fmaf_rn(s1, 1.0f, -C1);
            float S2 = __fmaf_rn(s2, 1.0f, -C2);
            FOLD(acc[r], S0, e0);
            FOLD(acc[r], S1, e1);
            FOLD(acc[r], S2, e2);
        }
    }

#pragma unroll
    for (int r = 0; r < 8; r++)
        g_proj[(size_t)(m0 + wid * 8 + r) * N_DIM + n0 + lane] = acc[r];
}

// ---------------------------------------------------------------------------
// Kernel 4: LIF scan (pinned unfused), coalesced spike writes [t][bo]
// ---------------------------------------------------------------------------
__global__ void scan_kernel() {
    int gid = blockIdx.x * blockDim.x + threadIdx.x;   // bo

    const float a_m = 0.95f, b_m = 0.05f, a_s = 0.8f;
    const float* pp = g_proj + gid;

    float V = 0.0f, I = 0.0f;
    for (int t = 0; t < TSTEPS; t++) {
        float p  = pp[(size_t)t * (NB * N_DIM)];
        float Vn = __fadd_rn(__fmul_rn(a_m, V), __fmul_rn(b_m, I));
        float In = __fadd_rn(__fmul_rn(a_s, I), p);
        bool  s  = (Vn > 1.0f);
        g_spk[(size_t)t * (NB * OUT_DIM) + gid] = s ? 1.0f : 0.0f;
        V = s ? 0.0f : Vn;
        I = In;
    }
}

// ---------------------------------------------------------------------------
// Kernel 5: transpose spikes [t][bo] -> out[bo][t]  (t=0 -> zeros)
// ---------------------------------------------------------------------------
__global__ void outw_kernel(float* __restrict__ out) {
    __shared__ float tl[32][33];
    int bo0 = blockIdx.x * 32;
    int t0  = blockIdx.y * 32;
    int tx = threadIdx.x, ty = threadIdx.y;

    int t = t0 + ty;
    float v = 0.0f;
    if (t >= 1 && t < STEPS)
        v = g_spk[(size_t)(t - 1) * (NB * OUT_DIM) + bo0 + tx];
    tl[ty][tx] = v;
    __syncthreads();

    int bo = bo0 + ty;
    int tt = t0 + tx;
    if (tt < STEPS)
        out[(size_t)bo * STEPS + tt] = tl[tx][ty];
}

// ---------------------------------------------------------------------------
extern "C" void kernel_launch(void* const* d_in, const int* in_sizes, int n_in,
                              void* d_out, int out_size) {
    const float* x = (const float*)d_in[0];   // [64][1024][100]
    const float* W = (const float*)d_in[1];   // [1024][1024]
    float* out = (float*)d_out;               // [64][1024][100]

    (void)in_sizes; (void)n_in; (void)out_size;

    mask_kernel<<<(M_ROWS + 7) / 8, 256>>>(x);
    wsplit_kernel<<<(N_DIM * K_DIM) / 256, 256>>>(W);

    dim3 gg(N_DIM / 32, M_ROWS / 32);         // (32, 198)
    gemm_kernel<<<gg, 128>>>();

    scan_kernel<<<(NB * OUT_DIM) / 256, 256>>>();

    dim3 ob(32, 32);
    dim3 og((NB * OUT_DIM) / 32, (STEPS + 31) / 32);
    outw_kernel<<<og, ob>>>(out);
}

// round 17
// speedup vs baseline: 2.3979x; 1.1422x over previous
#include <cuda_runtime.h>
#include <cuda_bf16.h>
#include <cstdint>

#define NB 64
#define IN_DIM 1024
#define OUT_DIM 1024
#define STEPS 100
#define TSTEPS 99
#define M_ROWS (TSTEPS * NB)    // 6336 = 198 * 32
#define K_DIM 1024
#define N_DIM 1024

typedef unsigned long long u64;

__device__ uint32_t g_xm[(size_t)M_ROWS * 32];        // [m][j] mask bits
__device__ float    g_ws0[(size_t)K_DIM * N_DIM];     // transposed [k][n]
__device__ float    g_ws1[(size_t)K_DIM * N_DIM];
__device__ float    g_ws2[(size_t)K_DIM * N_DIM];
__device__ float    g_proj[(size_t)M_ROWS * N_DIM];
__device__ float    g_spk[(size_t)TSTEPS * NB * OUT_DIM];

// Ladder constants per split
#define C0f 4.0f
#define C1f 0.015625f        // 2^-6
#define C2f 6.103515625e-5f  // 2^-14

// ---------------- packed f32x2 helpers (lanewise IEEE rn) ----------------
static __device__ __forceinline__ u64 padd(u64 a, u64 b) {
    u64 r; asm("add.rn.f32x2 %0, %1, %2;" : "=l"(r) : "l"(a), "l"(b)); return r;
}
static __device__ __forceinline__ u64 psub(u64 a, u64 b) {
    u64 r; asm("sub.rn.f32x2 %0, %1, %2;" : "=l"(r) : "l"(a), "l"(b)); return r;
}
static __device__ __forceinline__ u64 pset(float v) {
    u64 u = __float_as_uint(v);
    return (u << 32) | u;
}

// Ladder Fast2Sum (packed), identical per-lane arithmetic to R16 LADD
#define LADDP(s, e, b) do {      \
    u64 _t  = padd((s), (b));    \
    u64 _z  = psub(_t, (s));     \
    u64 _er = psub((b), _z);     \
    (e) = padd((e), _er);        \
    (s) = _t;                    \
} while (0)

// FOLD (packed), identical per-lane arithmetic to R16 FOLD
#define FOLDP(acc, S, e) do {            \
    u64 _t  = padd((acc), (S));          \
    u64 _b  = psub(_t, (acc));           \
    u64 _x  = psub(_t, _b);              \
    u64 _e1 = psub((acc), _x);           \
    u64 _e2 = psub((S), _b);             \
    u64 _er = padd(_e1, _e2);            \
    (acc) = padd(_t, padd(_er, (e)));    \
} while (0)

// ---------------------------------------------------------------------------
// Kernel 1: activation bitmasks. One warp per m=(t*64+b).
// ---------------------------------------------------------------------------
__global__ void mask_kernel(const float* __restrict__ x) {
    int m = blockIdx.x * 8 + (threadIdx.x >> 5);
    if (m >= M_ROWS) return;
    int lane = threadIdx.x & 31;
    int t = m >> 6, b = m & 63;
    const float* xb = x + (size_t)b * IN_DIM * STEPS + t;
    uint32_t* dst = g_xm + (size_t)m * 32;
#pragma unroll 4
    for (int j = 0; j < 32; j++) {
        float v = xb[(size_t)(j * 32 + lane) * STEPS];
        uint32_t msk = __ballot_sync(0xffffffffu, v != 0.0f);
        if (lane == 0) dst[j] = msk;
    }
}

// ---------------------------------------------------------------------------
// Kernel 2: split W into exact bf16 triple AND transpose to [k][n] planes.
// Block 32x32, shared-tile transpose, both sides coalesced.
// ---------------------------------------------------------------------------
__global__ void wsplit_kernel(const float* __restrict__ W) {
    __shared__ float t0[32][33], t1[32][33], t2[32][33];
    int n0 = blockIdx.x * 32, k0 = blockIdx.y * 32;
    int tx = threadIdx.x, ty = threadIdx.y;

    float w  = W[(size_t)(n0 + ty) * K_DIM + k0 + tx];
    float w0 = __bfloat162float(__float2bfloat16(w));
    float r1 = __fadd_rn(w, -w0);
    float w1 = __bfloat162float(__float2bfloat16(r1));
    float r2 = __fadd_rn(r1, -w1);
    float w2 = __bfloat162float(__float2bfloat16(r2));
    t0[ty][tx] = w0; t1[ty][tx] = w1; t2[ty][tx] = w2;
    __syncthreads();

    size_t o = (size_t)(k0 + ty) * N_DIM + n0 + tx;
    g_ws0[o] = t0[tx][ty];
    g_ws1[o] = t1[tx][ty];
    g_ws2[o] = t2[tx][ty];
}

// ---------------------------------------------------------------------------
// Kernel 3: bitwise bf16x9-emulation GEMM, mask-sparse, PACKED f32x2.
// Block: 32 m-rows x 64 n-cols, 128 thr; warp w -> rows 8w..8w+7,
// lane -> column pair (n0+2*lane, n0+2*lane+1). Mask loop shared per pair.
// ---------------------------------------------------------------------------
__global__ __launch_bounds__(128) void gemm_kernel() {
    __shared__ uint32_t Ms[32][32];
    __shared__ u64 sw0[16][33], sw1[16][33], sw2[16][33];   // float2 pairs

    int m0 = blockIdx.y * 32;
    int n0 = blockIdx.x * 64;
    int tid  = threadIdx.x;
    int lane = tid & 31;
    int wid  = tid >> 5;

    for (int i = tid; i < 32 * 32; i += 128)
        Ms[i >> 5][i & 31] = g_xm[(size_t)(m0 + (i >> 5)) * 32 + (i & 31)];

    const u64 PC0 = pset(C0f), PC1 = pset(C1f), PC2 = pset(C2f);

    u64 acc[8];
#pragma unroll
    for (int r = 0; r < 8; r++) acc[r] = 0ull;

    for (int c = 0; c < 64; c++) {
        __syncthreads();
        // stage W chunk pairs: 512 u64 per split, 4 per thread, coalesced
#pragma unroll
        for (int i = 0; i < 4; i++) {
            int idx = tid + i * 128;
            int k = idx >> 5, j = idx & 31;
            size_t src = (size_t)(c * 16 + k) * N_DIM + n0 + 2 * j;
            sw0[k][j] = *(const u64*)(g_ws0 + src);
            sw1[k][j] = *(const u64*)(g_ws1 + src);
            sw2[k][j] = *(const u64*)(g_ws2 + src);
        }
        __syncthreads();

        int jj = c >> 1, sh = (c & 1) << 4;
#pragma unroll
        for (int r = 0; r < 8; r++) {
            uint32_t mr = (Ms[wid * 8 + r][jj] >> sh) & 0xFFFFu;
            u64 s0 = PC0, s1 = PC1, s2 = PC2;
            u64 e0 = 0ull, e1 = 0ull, e2 = 0ull;
            while (mr) {                          // warp-uniform loop
                int k = __ffs(mr) - 1;
                mr &= mr - 1;
                u64 w0 = sw0[k][lane];
                u64 w1 = sw1[k][lane];
                u64 w2 = sw2[k][lane];
                LADDP(s0, e0, w0);
                LADDP(s1, e1, w1);
                LADDP(s2, e2, w2);
            }
            u64 S0 = psub(s0, PC0);               // Sterbenz-exact per lane
            u64 S1 = psub(s1, PC1);
            u64 S2 = psub(s2, PC2);
            FOLDP(acc[r], S0, e0);
            FOLDP(acc[r], S1, e1);
            FOLDP(acc[r], S2, e2);
        }
    }

#pragma unroll
    for (int r = 0; r < 8; r++)
        *(u64*)(g_proj + (size_t)(m0 + wid * 8 + r) * N_DIM + n0 + 2 * lane) = acc[r];
}

// ---------------------------------------------------------------------------
// Kernel 4: LIF scan (pinned unfused), coalesced spike writes [t][bo]
// ---------------------------------------------------------------------------
__global__ void scan_kernel() {
    int gid = blockIdx.x * blockDim.x + threadIdx.x;

    const float a_m = 0.95f, b_m = 0.05f, a_s = 0.8f;
    const float* pp = g_proj + gid;

    float V = 0.0f, I = 0.0f;
    for (int t = 0; t < TSTEPS; t++) {
        float p  = pp[(size_t)t * (NB * N_DIM)];
        float Vn = __fadd_rn(__fmul_rn(a_m, V), __fmul_rn(b_m, I));
        float In = __fadd_rn(__fmul_rn(a_s, I), p);
        bool  s  = (Vn > 1.0f);
        g_spk[(size_t)t * (NB * OUT_DIM) + gid] = s ? 1.0f : 0.0f;
        V = s ? 0.0f : Vn;
        I = In;
    }
}

// ---------------------------------------------------------------------------
// Kernel 5: transpose spikes [t][bo] -> out[bo][t]  (t=0 -> zeros)
// ---------------------------------------------------------------------------
__global__ void outw_kernel(float* __restrict__ out) {
    __shared__ float tl[32][33];
    int bo0 = blockIdx.x * 32;
    int t0  = blockIdx.y * 32;
    int tx = threadIdx.x, ty = threadIdx.y;

    int t = t0 + ty;
    float v = 0.0f;
    if (t >= 1 && t < STEPS)
        v = g_spk[(size_t)(t - 1) * (NB * OUT_DIM) + bo0 + tx];
    tl[ty][tx] = v;
    __syncthreads();

    int bo = bo0 + ty;
    int tt = t0 + tx;
    if (tt < STEPS)
        out[(size_t)bo * STEPS + tt] = tl[tx][ty];
}

// ---------------------------------------------------------------------------
extern "C" void kernel_launch(void* const* d_in, const int* in_sizes, int n_in,
                              void* d_out, int out_size) {
    const float* x = (const float*)d_in[0];   // [64][1024][100]
    const float* W = (const float*)d_in[1];   // [1024][1024]
    float* out = (float*)d_out;               // [64][1024][100]

    (void)in_sizes; (void)n_in; (void)out_size;

    mask_kernel<<<(M_ROWS + 7) / 8, 256>>>(x);

    dim3 wb(32, 32);
    dim3 wg(N_DIM / 32, K_DIM / 32);
    wsplit_kernel<<<wg, wb>>>(W);

    dim3 gg(N_DIM / 64, M_ROWS / 32);         // (16, 198)
    gemm_kernel<<<gg, 128>>>();

    scan_kernel<<<(NB * OUT_DIM) / 256, 256>>>();

    dim3 ob(32, 32);
    dim3 og((NB * OUT_DIM) / 32, (STEPS + 31) / 32);
    outw_kernel<<<og, ob>>>(out);
}